// round 16
// baseline (speedup 1.0000x reference)
#include <cuda_runtime.h>
#include <cstdint>

// ============================================================================
// QuantizedActorMLP fused-hybrid: EVERY CTA runs both engines.
//   warps 0-5 : int8 IMMA path (R13-proven), 6 x 16-row tiles = 96 rows
//   warps 6-7 : DP4A path (R2-proven), 64 threads x 1 row   = 64 rows
// 160 rows/CTA; per-SM resource mix is constant -> tensor & issue co-saturate.
// Unified input staging: rows padded to 32B (dp4a uses words 0..4, IMMA its
// fragment words). Requant math identical to the proven kernels.
// ============================================================================

#define ACT_SCALE 1.33f
#define QMAXF     127.0f
#define MAGIC     12582912.0f   // 1.5 * 2^23

// -------------------- DP4A-path constants (R2 layout) --------------------
struct QConst {
    int   W1[64 * 5];
    int   W2[64 * 16];
    int   W3[6 * 16];
    float b1s[64];
    float b2s[64];
    float b3[8];
    float G1, G2, G3;
};
__device__   QConst gQ;
__constant__ QConst cQ;

// -------------------- IMMA-path globals (R13 layout) --------------------
__device__ float    gG[3];
__device__ uint32_t gW1f[4 * 128];
__device__ uint32_t gW2f[8 * 128];
__device__ uint32_t gW3f[128];
__device__ float    gB1p[64];
__device__ float    gB2p[64];
__device__ float    gB3[8];

__device__ __forceinline__ int packq(int q0, int q1, int q2, int q3) {
    return __byte_perm(__byte_perm(q0, q1, 0x0040),
                       __byte_perm(q2, q3, 0x0040), 0x5410);
}

#define IMMA16832(Cv, Av, b0, b1)                                             \
    asm volatile(                                                             \
        "mma.sync.aligned.m16n8k32.row.col.s32.s8.s8.s32 "                    \
        "{%0,%1,%2,%3}, {%4,%5,%6,%7}, {%8,%9}, {%0,%1,%2,%3};"               \
        : "+r"((Cv)[0]), "+r"((Cv)[1]), "+r"((Cv)[2]), "+r"((Cv)[3])          \
        : "r"((Av)[0]), "r"((Av)[1]), "r"((Av)[2]), "r"((Av)[3]),             \
          "r"(b0), "r"(b1))

__device__ __forceinline__ int requant_magic(int acc, float G, float b) {
    float f = fmaf((float)acc, G, b);
    f = fminf(f, QMAXF);
    f = fmaxf(f, -QMAXF);
    return __float_as_int(__fadd_rn(f, MAGIC));
}

__device__ __forceinline__ int qw_s8(float w, float s) {
    float r = rintf(w / s);
    r = fminf(fmaxf(r, -QMAXF), QMAXF);
    return ((int)r) & 0xFF;
}

__device__ __forceinline__ int permN(int nt, int n) {
    return 16 * (nt >> 1) + 4 * (n >> 1) + 2 * (nt & 1) + (n & 1);
}

// ============================================================================
// Prep: scales, quantize weights; bake BOTH the dp4a pack and IMMA fragments.
// ============================================================================
__global__ void prep_kernel(const float* __restrict__ W1, const float* __restrict__ b1,
                            const float* __restrict__ W2, const float* __restrict__ b2,
                            const float* __restrict__ W3, const float* __restrict__ b3) {
    __shared__ float red[256];
    __shared__ float sS[3];
    const int tid = threadIdx.x;
    const float* Ws[3]  = {W1, W2, W3};
    const int    nel[3] = {64 * 17, 64 * 64, 6 * 64};

    for (int t = 0; t < 3; ++t) {
        float m = 0.0f;
        for (int i = tid; i < nel[t]; i += 256) m = fmaxf(m, fabsf(Ws[t][i]));
        red[tid] = m; __syncthreads();
        for (int s = 128; s > 0; s >>= 1) {
            if (tid < s) red[tid] = fmaxf(red[tid], red[tid + s]);
            __syncthreads();
        }
        if (tid == 0) sS[t] = red[0] / QMAXF;
        __syncthreads();
    }
    const float s1 = sS[0], s2 = sS[1], s3 = sS[2];
    const float step = ACT_SCALE / QMAXF;
    if (tid == 0) {
        gQ.G1 = s1; gQ.G2 = s2; gQ.G3 = step * s3;
        gG[0] = s1; gG[1] = s2; gG[2] = step * s3;
    }
    if (tid < 64) {
        gQ.b1s[tid] = b1[tid] / step;
        gQ.b2s[tid] = b2[tid] / step;
        int nt = tid >> 3, t = (tid >> 1) & 3, j = tid & 1;
        int l = 16 * (nt >> 1) + 4 * t + 2 * (nt & 1) + j;
        gB1p[tid] = b1[l] / step;
        gB2p[tid] = b2[l] / step;
    }
    if (tid < 8) {
        float v = (tid < 6) ? b3[tid] : 0.0f;
        gQ.b3[tid] = v; gB3[tid] = v;
    }

    // ---- dp4a pack (R2) ----
    for (int w = tid; w < 64 * 5; w += 256) {
        int j = w / 5, g = w % 5;
        int q[4];
#pragma unroll
        for (int b = 0; b < 4; ++b) {
            int k = 4 * g + b;
            int v = 0;
            if (k < 17) {
                float r = rintf(W1[j * 17 + k] / s1);
                v = (int)fminf(fmaxf(r, -QMAXF), QMAXF);
            }
            q[b] = v;
        }
        gQ.W1[w] = packq(q[0], q[1], q[2], q[3]);
    }
    for (int w = tid; w < 64 * 16; w += 256) {
        int j = w / 16, g = w % 16;
        int q[4];
#pragma unroll
        for (int b = 0; b < 4; ++b) {
            float r = rintf(W2[j * 64 + 4 * g + b] / s2);
            q[b] = (int)fminf(fmaxf(r, -QMAXF), QMAXF);
        }
        gQ.W2[w] = packq(q[0], q[1], q[2], q[3]);
    }
    for (int w = tid; w < 6 * 16; w += 256) {
        int k = w / 16, g = w % 16;
        int q[4];
#pragma unroll
        for (int b = 0; b < 4; ++b) {
            float r = rintf(W3[k * 64 + 4 * g + b] / s3);
            q[b] = (int)fminf(fmaxf(r, -QMAXF), QMAXF);
        }
        gQ.W3[w] = packq(q[0], q[1], q[2], q[3]);
    }

    // ---- IMMA fragments (R13) ----
    for (int idx = tid; idx < 4 * 128; idx += 256) {
        int m = idx >> 7, rem = idx & 127;
        int lane = rem >> 2, slot = rem & 3;
        int g = lane >> 2, t = lane & 3;
        int nt = 2 * m + (slot >> 1);
        int half = slot & 1;
        int n = permN(nt, g);
        int k0 = half * 16 + 4 * t;
        uint32_t word = 0;
#pragma unroll
        for (int i = 0; i < 4; ++i) {
            int k = k0 + i;
            int v = (k < 17) ? qw_s8(W1[n * 17 + k], s1) : 0;
            word |= (uint32_t)v << (8 * i);
        }
        gW1f[idx] = word;
    }
    for (int idx = tid; idx < 8 * 128; idx += 256) {
        int c = idx >> 7, rem = idx & 127;
        int lane = rem >> 2, slot = rem & 3;
        int g = lane >> 2, t = lane & 3;
        int kt = c >> 2, m = c & 3;
        int nt = 2 * m + (slot >> 1);
        int half = slot & 1;
        int n = permN(nt, g);
        int k0 = kt * 32 + half * 16 + 4 * t;
        uint32_t word = 0;
#pragma unroll
        for (int i = 0; i < 4; ++i)
            word |= (uint32_t)qw_s8(W2[(n << 6) + k0 + i], s2) << (8 * i);
        gW2f[idx] = word;
    }
    for (int idx = tid; idx < 128; idx += 256) {
        int lane = idx >> 2, slot = idx & 3;
        int g = lane >> 2, t = lane & 3;
        int kt = slot >> 1, half = slot & 1;
        int k0 = kt * 32 + half * 16 + 4 * t;
        uint32_t word = 0;
        if (g < 6) {
#pragma unroll
            for (int i = 0; i < 4; ++i)
                word |= (uint32_t)qw_s8(W3[(g << 6) + k0 + i], s3) << (8 * i);
        }
        gW3f[idx] = word;
    }
}

// ============================================================================
// Fused hybrid kernel: 160 rows/CTA (96 IMMA + 64 DP4A).
// ============================================================================
#define ROWS_CTA 160

__global__ __launch_bounds__(256, 6) void mlp_hybrid(
    const float* __restrict__ x, float* __restrict__ out, int B) {

    __shared__ __align__(16) unsigned char s_q[ROWS_CTA * 32];  // unified staging
    __shared__ uint32_t sW1[4 * 128];
    __shared__ uint32_t sW2[8 * 128];
    __shared__ uint32_t sW3[128];
    __shared__ float    sb1[64], sb2[64], sb3[8];

    const int tid  = threadIdx.x;
    const int warp = tid >> 5;
    const int lane = tid & 31;
    const int base = blockIdx.x * ROWS_CTA;
    const int rows = min(ROWS_CTA, B - base);
    const float INV = QMAXF / ACT_SCALE;

    // ---- stage IMMA weights + biases (all threads) ----
    for (int i = tid; i < 4 * 128; i += 256) sW1[i] = gW1f[i];
    for (int i = tid; i < 8 * 128; i += 256) sW2[i] = gW2f[i];
    if (tid < 128) sW3[tid] = gW3f[tid];
    if (tid < 64) { sb1[tid] = gB1p[tid]; sb2[tid] = gB2p[tid]; }
    if (tid < 8)  sb3[tid] = gB3[tid];

    // ---- unified input staging: quantize to bytes, rows padded to 32B ----
    for (int i = tid; i < ROWS_CTA * 8; i += 256) ((uint32_t*)s_q)[i] = 0u;
    __syncthreads();
    {
        const float* xg = x + (size_t)base * 17;
        const int n = rows * 17;
        for (int i = tid; i < n; i += 256) {
            float v = xg[i];
            v = fminf(fmaxf(v, -ACT_SCALE), ACT_SCALE);
            float q = fmaf(v, INV, MAGIC);          // RNE; low byte = int8
            int r = i / 17;
            int k = i - r * 17;
            s_q[r * 32 + k] = (unsigned char)__float_as_int(q);
        }
    }
    __syncthreads();

    if (warp < 6) {
        // ================= IMMA path: warps 0-5, local rows 0..95 =================
        const int g = lane >> 2;
        const int t = lane & 3;
        const float G1 = __ldg(&gG[0]);
        const float G2 = __ldg(&gG[1]);
        const float G3 = __ldg(&gG[2]);

        const int r0 = warp * 16 + g;

        uint32_t A1[4];
        {
            const unsigned char* p0 = s_q + r0 * 32;
            const unsigned char* p1 = s_q + (r0 + 8) * 32;
            A1[0] = *(const uint32_t*)(p0 + 4 * t);
            A1[1] = *(const uint32_t*)(p1 + 4 * t);
            A1[2] = *(const uint32_t*)(p0 + 16 + 4 * t);
            A1[3] = *(const uint32_t*)(p1 + 16 + 4 * t);
        }

        const float2* sb1v = (const float2*)sb1;
        const float2* sb2v = (const float2*)sb2;

        uint32_t A2[8];
#pragma unroll
        for (int m = 0; m < 4; ++m) {
            int C[2][4] = {{0, 0, 0, 0}, {0, 0, 0, 0}};
            uint4 w = *(const uint4*)&sW1[(m << 7) + (lane << 2)];
            IMMA16832(C[0], A1, w.x, w.y);
            IMMA16832(C[1], A1, w.z, w.w);
            const float2 bA = sb1v[(2 * m) * 4 + t];
            const float2 bB = sb1v[(2 * m + 1) * 4 + t];
            int pl0 = __byte_perm(requant_magic(C[0][0], G1, bA.x),
                                  requant_magic(C[0][1], G1, bA.y), 0x0040);
            int ph0 = __byte_perm(requant_magic(C[0][2], G1, bA.x),
                                  requant_magic(C[0][3], G1, bA.y), 0x0040);
            int pl1 = __byte_perm(requant_magic(C[1][0], G1, bB.x),
                                  requant_magic(C[1][1], G1, bB.y), 0x0040);
            int ph1 = __byte_perm(requant_magic(C[1][2], G1, bB.x),
                                  requant_magic(C[1][3], G1, bB.y), 0x0040);
            A2[2 * m]     = __byte_perm(pl0, pl1, 0x5410);
            A2[2 * m + 1] = __byte_perm(ph0, ph1, 0x5410);
        }

        uint32_t A3[8];
#pragma unroll
        for (int m = 0; m < 4; ++m) {
            int C[2][4] = {{0, 0, 0, 0}, {0, 0, 0, 0}};
#pragma unroll
            for (int kt = 0; kt < 2; ++kt) {
                uint4 w = *(const uint4*)&sW2[((kt * 4 + m) << 7) + (lane << 2)];
                IMMA16832(C[0], (A2 + 4 * kt), w.x, w.y);
                IMMA16832(C[1], (A2 + 4 * kt), w.z, w.w);
            }
            const float2 bA = sb2v[(2 * m) * 4 + t];
            const float2 bB = sb2v[(2 * m + 1) * 4 + t];
            int pl0 = __byte_perm(requant_magic(C[0][0], G2, bA.x),
                                  requant_magic(C[0][1], G2, bA.y), 0x0040);
            int ph0 = __byte_perm(requant_magic(C[0][2], G2, bA.x),
                                  requant_magic(C[0][3], G2, bA.y), 0x0040);
            int pl1 = __byte_perm(requant_magic(C[1][0], G2, bB.x),
                                  requant_magic(C[1][1], G2, bB.y), 0x0040);
            int ph1 = __byte_perm(requant_magic(C[1][2], G2, bB.x),
                                  requant_magic(C[1][3], G2, bB.y), 0x0040);
            A3[2 * m]     = __byte_perm(pl0, pl1, 0x5410);
            A3[2 * m + 1] = __byte_perm(ph0, ph1, 0x5410);
        }

        int D[4] = {0, 0, 0, 0};
        {
            uint4 w = *(const uint4*)&sW3[lane << 2];
            IMMA16832(D, (A3 + 0), w.x, w.y);
            IMMA16832(D, (A3 + 4), w.z, w.w);
        }

        if (t < 3) {
            const float2 b3p = *(const float2*)&sb3[2 * t];
            const int gr0 = base + r0;
            const int gr1 = gr0 + 8;
            if (gr0 < B) {
                float2 o;
                o.x = fmaf((float)D[0], G3, b3p.x);
                o.y = fmaf((float)D[1], G3, b3p.y);
                *(float2*)&out[(size_t)gr0 * 6 + 2 * t] = o;
            }
            if (gr1 < B) {
                float2 o;
                o.x = fmaf((float)D[2], G3, b3p.x);
                o.y = fmaf((float)D[3], G3, b3p.y);
                *(float2*)&out[(size_t)gr1 * 6 + 2 * t] = o;
            }
        }
    } else {
        // ================= DP4A path: warps 6-7, local rows 96..159 ===============
        const int ld   = tid - 192;           // 0..63
        const int grow = base + 96 + ld;
        if (grow < B) {
            const float G1 = cQ.G1, G2 = cQ.G2, G3 = cQ.G3;

            int p0[5];
            {
                const int* rp = (const int*)(s_q + (96 + ld) * 32);
#pragma unroll
                for (int g = 0; g < 5; ++g) p0[g] = rp[g];
            }

            int a1[16];
#pragma unroll
            for (int jw = 0; jw < 16; ++jw) {
                const float4 bb = *(const float4*)&cQ.b1s[jw * 4];
                const float bj[4] = {bb.x, bb.y, bb.z, bb.w};
                int q[4];
#pragma unroll
                for (int jj = 0; jj < 4; ++jj) {
                    const int j = jw * 4 + jj;
                    int acc = 0;
#pragma unroll
                    for (int g = 0; g < 5; ++g)
                        acc = __dp4a(p0[g], cQ.W1[j * 5 + g], acc);
                    float f = fmaf((float)acc, G1, bj[jj]);
                    int qi = __float2int_rn(f);
                    q[jj] = min(max(qi, -127), 127);
                }
                a1[jw] = packq(q[0], q[1], q[2], q[3]);
            }

            int acc3[6] = {0, 0, 0, 0, 0, 0};
#pragma unroll
            for (int jw = 0; jw < 16; ++jw) {
                const float4 bb = *(const float4*)&cQ.b2s[jw * 4];
                const float bj[4] = {bb.x, bb.y, bb.z, bb.w};
                int q[4];
#pragma unroll
                for (int jj = 0; jj < 4; ++jj) {
                    const int j = jw * 4 + jj;
                    int acc = 0;
#pragma unroll
                    for (int g = 0; g < 4; ++g) {
                        const int4 w = *(const int4*)&cQ.W2[j * 16 + g * 4];
                        acc = __dp4a(a1[g * 4 + 0], w.x, acc);
                        acc = __dp4a(a1[g * 4 + 1], w.y, acc);
                        acc = __dp4a(a1[g * 4 + 2], w.z, acc);
                        acc = __dp4a(a1[g * 4 + 3], w.w, acc);
                    }
                    float f = fmaf((float)acc, G2, bj[jj]);
                    int qi = __float2int_rn(f);
                    q[jj] = min(max(qi, -127), 127);
                }
                const int a2w = packq(q[0], q[1], q[2], q[3]);
#pragma unroll
                for (int k = 0; k < 6; ++k)
                    acc3[k] = __dp4a(a2w, cQ.W3[k * 16 + jw], acc3[k]);
            }

            // direct output: 3 x float2 per row
            float o[6];
#pragma unroll
            for (int k = 0; k < 6; ++k)
                o[k] = fmaf((float)acc3[k], G3, cQ.b3[k]);
            float2* og = (float2*)&out[(size_t)grow * 6];
            og[0] = make_float2(o[0], o[1]);
            og[1] = make_float2(o[2], o[3]);
            og[2] = make_float2(o[4], o[5]);
        }
    }
}

extern "C" void kernel_launch(void* const* d_in, const int* in_sizes, int n_in,
                              void* d_out, int out_size) {
    const float* x  = (const float*)d_in[0];
    const float* W1 = (const float*)d_in[1];
    const float* b1 = (const float*)d_in[2];
    const float* W2 = (const float*)d_in[3];
    const float* b2 = (const float*)d_in[4];
    const float* W3 = (const float*)d_in[5];
    const float* b3 = (const float*)d_in[6];
    float* out = (float*)d_out;

    const int B = in_sizes[0] / 17;
    const int blocks = (B + ROWS_CTA - 1) / ROWS_CTA;

    prep_kernel<<<1, 256>>>(W1, b1, W2, b2, W3, b3);

    void* gq_ptr = nullptr;
    cudaGetSymbolAddress(&gq_ptr, gQ);
    cudaMemcpyToSymbolAsync(cQ, gq_ptr, sizeof(QConst), 0,
                            cudaMemcpyDeviceToDevice, 0);

    mlp_hybrid<<<blocks, 256>>>(x, out, B);
}

// round 17
// speedup vs baseline: 1.0458x; 1.0458x over previous
#include <cuda_runtime.h>
#include <cstdint>

// ============================================================================
// QuantizedActorMLP hybrid v3 (block-level, R15 base): 2/3 rows on int8 IMMA,
// 1/3 on DP4A. Round 17: shrink SASS footprint — dp4a layer-2/3 is a rolled
// loop (16 iters, indexed LDC) to stop L0/L1.5 I$ thrash when both code paths
// run concurrently per SM. All math identical to the proven kernels.
// Pattern period 5 blocks = [I(128) x4, D(256)] over 768 rows.
// ============================================================================

#define ACT_SCALE 1.33f
#define QMAXF     127.0f
#define MAGIC     12582912.0f   // 1.5 * 2^23

// -------------------- DP4A-path constants (R2 layout) --------------------
struct QConst {
    int   W1[64 * 5];
    int   W2[64 * 16];
    int   W3T[16 * 8];   // TRANSPOSED: [jw][k], k<6 real, k>=6 zero
    float b1s[64];
    float b2s[64];
    float b3[8];
    float G1, G2, G3;
};
__device__   QConst gQ;
__constant__ QConst cQ;

// -------------------- IMMA-path globals (R13 layout) --------------------
__device__ float    gG[3];
__device__ uint32_t gW1f[4 * 128];
__device__ uint32_t gW2f[8 * 128];
__device__ uint32_t gW3f[128];
__device__ float    gB1p[64];
__device__ float    gB2p[64];
__device__ float    gB3[8];

__device__ __forceinline__ int packq(int q0, int q1, int q2, int q3) {
    return __byte_perm(__byte_perm(q0, q1, 0x0040),
                       __byte_perm(q2, q3, 0x0040), 0x5410);
}

#define IMMA16832(Cv, Av, b0, b1)                                             \
    asm volatile(                                                             \
        "mma.sync.aligned.m16n8k32.row.col.s32.s8.s8.s32 "                    \
        "{%0,%1,%2,%3}, {%4,%5,%6,%7}, {%8,%9}, {%0,%1,%2,%3};"               \
        : "+r"((Cv)[0]), "+r"((Cv)[1]), "+r"((Cv)[2]), "+r"((Cv)[3])          \
        : "r"((Av)[0]), "r"((Av)[1]), "r"((Av)[2]), "r"((Av)[3]),             \
          "r"(b0), "r"(b1))

__device__ __forceinline__ int requant_magic(int acc, float G, float b) {
    float f = fmaf((float)acc, G, b);
    f = fminf(f, QMAXF);
    f = fmaxf(f, -QMAXF);
    return __float_as_int(__fadd_rn(f, MAGIC));
}

__device__ __forceinline__ int qw_s8(float w, float s) {
    float r = rintf(w / s);
    r = fminf(fmaxf(r, -QMAXF), QMAXF);
    return ((int)r) & 0xFF;
}

__device__ __forceinline__ int permN(int nt, int n) {
    return 16 * (nt >> 1) + 4 * (n >> 1) + 2 * (nt & 1) + (n & 1);
}

// ============================================================================
// Prep: scales, quantize weights; bake dp4a pack (W3 transposed) + IMMA frags.
// ============================================================================
__global__ void prep_kernel(const float* __restrict__ W1, const float* __restrict__ b1,
                            const float* __restrict__ W2, const float* __restrict__ b2,
                            const float* __restrict__ W3, const float* __restrict__ b3) {
    __shared__ float red[256];
    __shared__ float sS[3];
    const int tid = threadIdx.x;
    const float* Ws[3]  = {W1, W2, W3};
    const int    nel[3] = {64 * 17, 64 * 64, 6 * 64};

    for (int t = 0; t < 3; ++t) {
        float m = 0.0f;
        for (int i = tid; i < nel[t]; i += 256) m = fmaxf(m, fabsf(Ws[t][i]));
        red[tid] = m; __syncthreads();
        for (int s = 128; s > 0; s >>= 1) {
            if (tid < s) red[tid] = fmaxf(red[tid], red[tid + s]);
            __syncthreads();
        }
        if (tid == 0) sS[t] = red[0] / QMAXF;
        __syncthreads();
    }
    const float s1 = sS[0], s2 = sS[1], s3 = sS[2];
    const float step = ACT_SCALE / QMAXF;
    if (tid == 0) {
        gQ.G1 = s1; gQ.G2 = s2; gQ.G3 = step * s3;
        gG[0] = s1; gG[1] = s2; gG[2] = step * s3;
    }
    if (tid < 64) {
        gQ.b1s[tid] = b1[tid] / step;
        gQ.b2s[tid] = b2[tid] / step;
        int nt = tid >> 3, t = (tid >> 1) & 3, j = tid & 1;
        int l = 16 * (nt >> 1) + 4 * t + 2 * (nt & 1) + j;
        gB1p[tid] = b1[l] / step;
        gB2p[tid] = b2[l] / step;
    }
    if (tid < 8) {
        float v = (tid < 6) ? b3[tid] : 0.0f;
        gQ.b3[tid] = v; gB3[tid] = v;
    }

    // ---- dp4a pack ----
    for (int w = tid; w < 64 * 5; w += 256) {
        int j = w / 5, g = w % 5;
        int q[4];
#pragma unroll
        for (int b = 0; b < 4; ++b) {
            int k = 4 * g + b;
            int v = 0;
            if (k < 17) {
                float r = rintf(W1[j * 17 + k] / s1);
                v = (int)fminf(fmaxf(r, -QMAXF), QMAXF);
            }
            q[b] = v;
        }
        gQ.W1[w] = packq(q[0], q[1], q[2], q[3]);
    }
    for (int w = tid; w < 64 * 16; w += 256) {
        int j = w / 16, g = w % 16;
        int q[4];
#pragma unroll
        for (int b = 0; b < 4; ++b) {
            float r = rintf(W2[j * 64 + 4 * g + b] / s2);
            q[b] = (int)fminf(fmaxf(r, -QMAXF), QMAXF);
        }
        gQ.W2[w] = packq(q[0], q[1], q[2], q[3]);
    }
    // W3 TRANSPOSED: W3T[jw][k] = packed word of W3 row k, cols 4jw..4jw+3
    for (int w = tid; w < 16 * 8; w += 256) {
        int jw = w >> 3, k = w & 7;
        int word = 0;
        if (k < 6) {
            int q[4];
#pragma unroll
            for (int b = 0; b < 4; ++b) {
                float r = rintf(W3[k * 64 + 4 * jw + b] / s3);
                q[b] = (int)fminf(fmaxf(r, -QMAXF), QMAXF);
            }
            word = packq(q[0], q[1], q[2], q[3]);
        }
        gQ.W3T[w] = word;
    }

    // ---- IMMA fragments (R13) ----
    for (int idx = tid; idx < 4 * 128; idx += 256) {
        int m = idx >> 7, rem = idx & 127;
        int lane = rem >> 2, slot = rem & 3;
        int g = lane >> 2, t = lane & 3;
        int nt = 2 * m + (slot >> 1);
        int half = slot & 1;
        int n = permN(nt, g);
        int k0 = half * 16 + 4 * t;
        uint32_t word = 0;
#pragma unroll
        for (int i = 0; i < 4; ++i) {
            int k = k0 + i;
            int v = (k < 17) ? qw_s8(W1[n * 17 + k], s1) : 0;
            word |= (uint32_t)v << (8 * i);
        }
        gW1f[idx] = word;
    }
    for (int idx = tid; idx < 8 * 128; idx += 256) {
        int c = idx >> 7, rem = idx & 127;
        int lane = rem >> 2, slot = rem & 3;
        int g = lane >> 2, t = lane & 3;
        int kt = c >> 2, m = c & 3;
        int nt = 2 * m + (slot >> 1);
        int half = slot & 1;
        int n = permN(nt, g);
        int k0 = kt * 32 + half * 16 + 4 * t;
        uint32_t word = 0;
#pragma unroll
        for (int i = 0; i < 4; ++i)
            word |= (uint32_t)qw_s8(W2[(n << 6) + k0 + i], s2) << (8 * i);
        gW2f[idx] = word;
    }
    for (int idx = tid; idx < 128; idx += 256) {
        int lane = idx >> 2, slot = idx & 3;
        int g = lane >> 2, t = lane & 3;
        int kt = slot >> 1, half = slot & 1;
        int k0 = kt * 32 + half * 16 + 4 * t;
        uint32_t word = 0;
        if (g < 6) {
#pragma unroll
            for (int i = 0; i < 4; ++i)
                word |= (uint32_t)qw_s8(W3[(g << 6) + k0 + i], s3) << (8 * i);
        }
        gW3f[idx] = word;
    }
}

// ============================================================================
// Hybrid kernel, UNIONED smem, compact code. Pattern period 5 = 768 rows.
// ============================================================================
#define SM_BYTES 11392

__global__ __launch_bounds__(256, 6) void mlp_hybrid(
    const float* __restrict__ x, float* __restrict__ out, int B) {

    __shared__ __align__(16) unsigned char sm[SM_BYTES];

    const int tid = threadIdx.x;
    const int pat = blockIdx.x % 5;
    const int grp = blockIdx.x / 5;
    const float INV = QMAXF / ACT_SCALE;

    if (pat < 4) {
        // ================= IMMA path (R13-proven, unchanged) =================
        unsigned char* s_iq = sm;
        uint32_t* sW1 = (uint32_t*)(sm + 4096);
        uint32_t* sW2 = (uint32_t*)(sm + 6144);
        uint32_t* sW3 = (uint32_t*)(sm + 10240);
        float* sb1 = (float*)(sm + 10752);
        float* sb2 = (float*)(sm + 11008);
        float* sb3 = (float*)(sm + 11264);

        const int rowbase = grp * 768 + pat * 128;
        if (rowbase >= B) return;
        const int rows = min(128, B - rowbase);

        const int warp = tid >> 5;
        const int lane = tid & 31;
        const int g    = lane >> 2;
        const int t    = lane & 3;

        for (int i = tid; i < 4 * 128; i += 256) sW1[i] = gW1f[i];
        for (int i = tid; i < 8 * 128; i += 256) sW2[i] = gW2f[i];
        if (tid < 128) sW3[tid] = gW3f[tid];
        if (tid < 64) { sb1[tid] = gB1p[tid]; sb2[tid] = gB2p[tid]; }
        if (tid < 8)  sb3[tid] = gB3[tid];

        for (int i = tid; i < 1024; i += 256) ((uint32_t*)s_iq)[i] = 0u;
        __syncthreads();
        {
            const float* xg = x + (size_t)rowbase * 17;
            const int n = rows * 17;
            for (int i = tid; i < n; i += 256) {
                float v = xg[i];
                v = fminf(fmaxf(v, -ACT_SCALE), ACT_SCALE);
                float q = fmaf(v, INV, MAGIC);
                int r = i / 17;
                int k = i - r * 17;
                s_iq[r * 32 + k] = (unsigned char)__float_as_int(q);
            }
        }
        __syncthreads();

        const float G1 = __ldg(&gG[0]);
        const float G2 = __ldg(&gG[1]);
        const float G3 = __ldg(&gG[2]);

        const int r0 = warp * 16 + g;

        uint32_t A1[4];
        {
            const unsigned char* p0 = s_iq + r0 * 32;
            const unsigned char* p1 = s_iq + (r0 + 8) * 32;
            A1[0] = *(const uint32_t*)(p0 + 4 * t);
            A1[1] = *(const uint32_t*)(p1 + 4 * t);
            A1[2] = *(const uint32_t*)(p0 + 16 + 4 * t);
            A1[3] = *(const uint32_t*)(p1 + 16 + 4 * t);
        }

        const float2* sb1v = (const float2*)sb1;
        const float2* sb2v = (const float2*)sb2;

        uint32_t A2[8];
#pragma unroll
        for (int m = 0; m < 4; ++m) {
            int C[2][4] = {{0, 0, 0, 0}, {0, 0, 0, 0}};
            uint4 w = *(const uint4*)&sW1[(m << 7) + (lane << 2)];
            IMMA16832(C[0], A1, w.x, w.y);
            IMMA16832(C[1], A1, w.z, w.w);
            const float2 bA = sb1v[(2 * m) * 4 + t];
            const float2 bB = sb1v[(2 * m + 1) * 4 + t];
            int pl0 = __byte_perm(requant_magic(C[0][0], G1, bA.x),
                                  requant_magic(C[0][1], G1, bA.y), 0x0040);
            int ph0 = __byte_perm(requant_magic(C[0][2], G1, bA.x),
                                  requant_magic(C[0][3], G1, bA.y), 0x0040);
            int pl1 = __byte_perm(requant_magic(C[1][0], G1, bB.x),
                                  requant_magic(C[1][1], G1, bB.y), 0x0040);
            int ph1 = __byte_perm(requant_magic(C[1][2], G1, bB.x),
                                  requant_magic(C[1][3], G1, bB.y), 0x0040);
            A2[2 * m]     = __byte_perm(pl0, pl1, 0x5410);
            A2[2 * m + 1] = __byte_perm(ph0, ph1, 0x5410);
        }

        uint32_t A3[8];
#pragma unroll
        for (int m = 0; m < 4; ++m) {
            int C[2][4] = {{0, 0, 0, 0}, {0, 0, 0, 0}};
#pragma unroll
            for (int kt = 0; kt < 2; ++kt) {
                uint4 w = *(const uint4*)&sW2[((kt * 4 + m) << 7) + (lane << 2)];
                IMMA16832(C[0], (A2 + 4 * kt), w.x, w.y);
                IMMA16832(C[1], (A2 + 4 * kt), w.z, w.w);
            }
            const float2 bA = sb2v[(2 * m) * 4 + t];
            const float2 bB = sb2v[(2 * m + 1) * 4 + t];
            int pl0 = __byte_perm(requant_magic(C[0][0], G2, bA.x),
                                  requant_magic(C[0][1], G2, bA.y), 0x0040);
            int ph0 = __byte_perm(requant_magic(C[0][2], G2, bA.x),
                                  requant_magic(C[0][3], G2, bA.y), 0x0040);
            int pl1 = __byte_perm(requant_magic(C[1][0], G2, bB.x),
                                  requant_magic(C[1][1], G2, bB.y), 0x0040);
            int ph1 = __byte_perm(requant_magic(C[1][2], G2, bB.x),
                                  requant_magic(C[1][3], G2, bB.y), 0x0040);
            A3[2 * m]     = __byte_perm(pl0, pl1, 0x5410);
            A3[2 * m + 1] = __byte_perm(ph0, ph1, 0x5410);
        }

        int D[4] = {0, 0, 0, 0};
        {
            uint4 w = *(const uint4*)&sW3[lane << 2];
            IMMA16832(D, (A3 + 0), w.x, w.y);
            IMMA16832(D, (A3 + 4), w.z, w.w);
        }

        if (t < 3) {
            const float2 b3p = *(const float2*)&sb3[2 * t];
            const int gr0 = rowbase + r0;
            const int gr1 = gr0 + 8;
            if (gr0 < B) {
                float2 o;
                o.x = fmaf((float)D[0], G3, b3p.x);
                o.y = fmaf((float)D[1], G3, b3p.y);
                *(float2*)&out[(size_t)gr0 * 6 + 2 * t] = o;
            }
            if (gr1 < B) {
                float2 o;
                o.x = fmaf((float)D[2], G3, b3p.x);
                o.y = fmaf((float)D[3], G3, b3p.y);
                *(float2*)&out[(size_t)gr1 * 6 + 2 * t] = o;
            }
        }
    } else {
        // ================= DP4A path (compact code: rolled L2/L3) =================
        unsigned char* s_dq = sm;
        float* s_out = (float*)(sm + 5120);

        const int base = grp * 768 + 512;
        if (base >= B) return;
        const int rows = min(256, B - base);

        for (int i = tid; i < 1280; i += 256) ((int*)s_dq)[i] = 0;
        __syncthreads();
        {
            const float* xg = x + (size_t)base * 17;
            const int n = rows * 17;
            for (int i = tid; i < n; i += 256) {
                float v = xg[i];
                v = fminf(fmaxf(v, -ACT_SCALE), ACT_SCALE);
                int q = __float2int_rn(v * INV);
                int r = i / 17;
                int k = i - r * 17;
                s_dq[r * 20 + k] = (unsigned char)q;
            }
        }
        __syncthreads();

        if (tid < rows) {
            const float G1 = cQ.G1, G2 = cQ.G2, G3 = cQ.G3;

            int p0[5];
            {
                const int* rp = (const int*)(s_dq + tid * 20);
#pragma unroll
                for (int g = 0; g < 5; ++g) p0[g] = rp[g];
            }

            // ---- layer 1 (unrolled: a1[] needs static indices) ----
            int a1[16];
#pragma unroll
            for (int jw = 0; jw < 16; ++jw) {
                const float4 bb = *(const float4*)&cQ.b1s[jw * 4];
                const float bj[4] = {bb.x, bb.y, bb.z, bb.w};
                int q[4];
#pragma unroll
                for (int jj = 0; jj < 4; ++jj) {
                    const int j = jw * 4 + jj;
                    int acc = 0;
#pragma unroll
                    for (int g = 0; g < 5; ++g)
                        acc = __dp4a(p0[g], cQ.W1[j * 5 + g], acc);
                    float f = fmaf((float)acc, G1, bj[jj]);
                    int qi = __float2int_rn(f);
                    q[jj] = min(max(qi, -127), 127);
                }
                a1[jw] = packq(q[0], q[1], q[2], q[3]);
            }

            // ---- layer 2 + 3: ROLLED loop (16 iters) — small I$ footprint ----
            int acc3[6] = {0, 0, 0, 0, 0, 0};
#pragma unroll 1
            for (int jw = 0; jw < 16; ++jw) {
                const float4 bb = *(const float4*)&cQ.b2s[jw * 4];
                const float bj[4] = {bb.x, bb.y, bb.z, bb.w};
                int q[4];
#pragma unroll
                for (int jj = 0; jj < 4; ++jj) {
                    const int j = jw * 4 + jj;
                    int acc = 0;
#pragma unroll
                    for (int g = 0; g < 4; ++g) {
                        const int4 w = *(const int4*)&cQ.W2[j * 16 + g * 4];
                        acc = __dp4a(a1[g * 4 + 0], w.x, acc);
                        acc = __dp4a(a1[g * 4 + 1], w.y, acc);
                        acc = __dp4a(a1[g * 4 + 2], w.z, acc);
                        acc = __dp4a(a1[g * 4 + 3], w.w, acc);
                    }
                    float f = fmaf((float)acc, G2, bj[jj]);
                    int qi = __float2int_rn(f);
                    q[jj] = min(max(qi, -127), 127);
                }
                const int a2w = packq(q[0], q[1], q[2], q[3]);
                const int4 w3lo = *(const int4*)&cQ.W3T[jw * 8];
                const int2 w3hi = *(const int2*)&cQ.W3T[jw * 8 + 4];
                acc3[0] = __dp4a(a2w, w3lo.x, acc3[0]);
                acc3[1] = __dp4a(a2w, w3lo.y, acc3[1]);
                acc3[2] = __dp4a(a2w, w3lo.z, acc3[2]);
                acc3[3] = __dp4a(a2w, w3lo.w, acc3[3]);
                acc3[4] = __dp4a(a2w, w3hi.x, acc3[4]);
                acc3[5] = __dp4a(a2w, w3hi.y, acc3[5]);
            }

#pragma unroll
            for (int k = 0; k < 6; ++k)
                s_out[tid * 6 + k] = fmaf((float)acc3[k], G3, cQ.b3[k]);
        }
        __syncthreads();

        float* og = out + (size_t)base * 6;
        if (rows == 256) {
            float4* ov = (float4*)og;
            const float4* sv = (const float4*)s_out;
            for (int i = tid; i < 384; i += 256) ov[i] = sv[i];
        } else {
            const int nf = rows * 6;
            for (int i = tid; i < nf; i += 256) og[i] = s_out[i];
        }
    }
}

extern "C" void kernel_launch(void* const* d_in, const int* in_sizes, int n_in,
                              void* d_out, int out_size) {
    const float* x  = (const float*)d_in[0];
    const float* W1 = (const float*)d_in[1];
    const float* b1 = (const float*)d_in[2];
    const float* W2 = (const float*)d_in[3];
    const float* b2 = (const float*)d_in[4];
    const float* W3 = (const float*)d_in[5];
    const float* b3 = (const float*)d_in[6];
    float* out = (float*)d_out;

    const int B = in_sizes[0] / 17;
    const int groups = (B + 767) / 768;

    prep_kernel<<<1, 256>>>(W1, b1, W2, b2, W3, b3);

    void* gq_ptr = nullptr;
    cudaGetSymbolAddress(&gq_ptr, gQ);
    cudaMemcpyToSymbolAsync(cQ, gq_ptr, sizeof(QConst), 0,
                            cudaMemcpyDeviceToDevice, 0);

    mlp_hybrid<<<groups * 5, 256>>>(x, out, B);
}